// round 6
// baseline (speedup 1.0000x reference)
#include <cuda_runtime.h>
#include <cstdint>

#define NN 50000
#define NE 800000

// Scratch (allocation-free rule: __device__ globals)
__device__ float g_agg1[NN * 128];
__device__ float g_x1[NN * 128];
__device__ float g_agg2[NN * 128];
__device__ int g_is64;
__device__ int g_deg[NN];
__device__ int g_rowptr[NN + 1];
__device__ int g_cur[NN];
__device__ int g_esrc[NE];

__device__ __forceinline__ unsigned long long pack2(float x) {
    unsigned long long r;
    asm("mov.b64 %0, {%1, %1};" : "=l"(r) : "f"(x));
    return r;
}
__device__ __forceinline__ float2 unpack2(unsigned long long v) {
    float2 r;
    asm("mov.b64 {%0, %1}, %2;" : "=f"(r.x), "=f"(r.y) : "l"(v));
    return r;
}
__device__ __forceinline__ void fma2(unsigned long long& acc, unsigned long long a, unsigned long long b) {
    asm("fma.rn.f32x2 %0, %1, %2, %0;" : "+l"(acc) : "l"(a), "l"(b));
}

// ======================= CSR build =======================
__global__ void detect_and_zero_kernel(const int* __restrict__ w) {
    int i = blockIdx.x * blockDim.x + threadIdx.x;
    for (int k = i; k < NN; k += gridDim.x * blockDim.x) g_deg[k] = 0;
    if (blockIdx.x == 0) {
        __shared__ int any;
        if (threadIdx.x == 0) any = 0;
        __syncthreads();
        int nz = 0;
        for (int k = threadIdx.x; k < 1024; k += blockDim.x) nz |= __ldg(w + 2 * k + 1);
        if (nz) any = 1;
        __syncthreads();
        if (threadIdx.x == 0) g_is64 = any ? 0 : 1;
    }
}

__device__ __forceinline__ void load_edge(const void* ei_raw, int e, int& src, int& dst) {
    if (g_is64) {
        const long long* ei = (const long long*)ei_raw;
        src = (int)__ldg(ei + e);
        dst = (int)__ldg(ei + NE + e);
    } else {
        const int* ei = (const int*)ei_raw;
        src = __ldg(ei + e);
        dst = __ldg(ei + NE + e);
    }
}

__global__ void hist_kernel(const void* __restrict__ ei_raw) {
    int e = blockIdx.x * blockDim.x + threadIdx.x;
    if (e < NE) {
        int src, dst;
        load_edge(ei_raw, e, src, dst);
        atomicAdd(&g_deg[dst], 1);
    }
}

// single-block exclusive scan: rowptr/cur from deg
__global__ void scan_kernel() {
    __shared__ int part[1024];
    const int tid = threadIdx.x;
    const int CH = (NN + 1023) / 1024;  // 49
    int base = tid * CH;
    int s = 0;
#pragma unroll 4
    for (int i = 0; i < CH; i++) {
        int idx = base + i;
        if (idx < NN) s += g_deg[idx];
    }
    part[tid] = s;
    __syncthreads();
    for (int off = 1; off < 1024; off <<= 1) {
        int t = (tid >= off) ? part[tid - off] : 0;
        __syncthreads();
        part[tid] += t;
        __syncthreads();
    }
    int run = part[tid] - s;  // exclusive prefix
    for (int i = 0; i < CH; i++) {
        int idx = base + i;
        if (idx < NN) {
            g_rowptr[idx] = run;
            g_cur[idx] = run;
            run += g_deg[idx];
        }
    }
    if (tid == 0) g_rowptr[NN] = NE;
}

__global__ void fill_kernel(const void* __restrict__ ei_raw) {
    int e = blockIdx.x * blockDim.x + threadIdx.x;
    if (e < NE) {
        int src, dst;
        load_edge(ei_raw, e, src, dst);
        int p = atomicAdd(&g_cur[dst], 1);
        g_esrc[p] = src;
    }
}

// ======================= CSR aggregation =======================
// One warp per node: agg[i] = (1+eps)*x[i] + sum_{j in N(i)} x[j]
__global__ void agg_kernel(const float* __restrict__ x,
                           const float* __restrict__ eps,
                           float* __restrict__ agg) {
    int node = blockIdx.x * (blockDim.x >> 5) + (threadIdx.x >> 5);
    if (node >= NN) return;
    int lane = threadIdx.x & 31;
    float s = 1.0f + __ldg(eps);
    int beg = __ldg(g_rowptr + node), end = __ldg(g_rowptr + node + 1);

    float4 a = __ldg((const float4*)(x + (size_t)node * 128) + lane);
    float4 acc = make_float4(s * a.x, s * a.y, s * a.z, s * a.w);

    int j = beg;
    for (; j + 4 <= end; j += 4) {
        int s0 = __ldg(g_esrc + j), s1 = __ldg(g_esrc + j + 1);
        int s2 = __ldg(g_esrc + j + 2), s3 = __ldg(g_esrc + j + 3);
        float4 v0 = __ldg((const float4*)(x + (size_t)s0 * 128) + lane);
        float4 v1 = __ldg((const float4*)(x + (size_t)s1 * 128) + lane);
        float4 v2 = __ldg((const float4*)(x + (size_t)s2 * 128) + lane);
        float4 v3 = __ldg((const float4*)(x + (size_t)s3 * 128) + lane);
        acc.x += v0.x + v1.x; acc.y += v0.y + v1.y;
        acc.z += v0.z + v1.z; acc.w += v0.w + v1.w;
        acc.x += v2.x + v3.x; acc.y += v2.y + v3.y;
        acc.z += v2.z + v3.z; acc.w += v2.w + v3.w;
    }
    for (; j < end; j++) {
        int s0 = __ldg(g_esrc + j);
        float4 v = __ldg((const float4*)(x + (size_t)s0 * 128) + lane);
        acc.x += v.x; acc.y += v.y; acc.z += v.z; acc.w += v.w;
    }
    ((float4*)(agg + (size_t)node * 128))[lane] = acc;
}

// ===================== fused MLP: 128x128 tile, 512 thr, 4x8/thread, FFMA2 =====================
#define F_W1  0                       // [128][132] transposed: sW[k*132+c] = w[c*128+k]
#define F_W2  (128 * 132)
#define F_AT  (2 * 128 * 132)         // [128][128] A tile, reused as T tile
#define F_BA  (F_AT + 128 * 128)
#define F_BB  (F_BA + 128)
#define SMEM_FLOATS (F_BB + 128)
#define SMEM_BYTES (SMEM_FLOATS * 4)  // 201728 B

// acc[i][j]: rows r0+i (i<4), col pair c0+2j (j<4 -> 8 cols)
__device__ __forceinline__ void do_gemm(const float* __restrict__ sA,
                                        const float* __restrict__ sW,
                                        int r0, int c0,
                                        unsigned long long acc[4][4]) {
#pragma unroll
    for (int i = 0; i < 4; i++)
#pragma unroll
        for (int j = 0; j < 4; j++) acc[i][j] = 0ull;

#pragma unroll 4
    for (int k4 = 0; k4 < 128; k4 += 4) {
        float4 a[4];
#pragma unroll
        for (int i = 0; i < 4; i++)
            a[i] = *(const float4*)(sA + (r0 + i) * 128 + k4);
        const float* af = (const float*)a;
#pragma unroll
        for (int kk = 0; kk < 4; kk++) {
            ulonglong2 b0 = *(const ulonglong2*)(sW + (k4 + kk) * 132 + c0);
            ulonglong2 b1 = *(const ulonglong2*)(sW + (k4 + kk) * 132 + c0 + 4);
#pragma unroll
            for (int i = 0; i < 4; i++) {
                unsigned long long av = pack2(af[i * 4 + kk]);
                fma2(acc[i][0], av, b0.x);
                fma2(acc[i][1], av, b0.y);
                fma2(acc[i][2], av, b1.x);
                fma2(acc[i][3], av, b1.y);
            }
        }
    }
}

template <bool RELU_OUT>
__global__ void __launch_bounds__(512, 1)
mlp_kernel(const float* __restrict__ H,
           const float* __restrict__ wA, const float* __restrict__ bA,
           const float* __restrict__ wB, const float* __restrict__ bB,
           float* __restrict__ out) {
    extern __shared__ float sm[];
    float* sW1 = sm + F_W1;
    float* sW2 = sm + F_W2;
    float* sAT = sm + F_AT;
    float* ba  = sm + F_BA;
    float* bb  = sm + F_BB;
    const int tid = threadIdx.x;

    for (int i = tid; i < 128 * 128; i += 512) {
        int c = i >> 7, k = i & 127;
        sW1[k * 132 + c] = __ldg(wA + i);
        sW2[k * 132 + c] = __ldg(wB + i);
    }
    if (tid < 128) {
        ba[tid] = __ldg(bA + tid);
        bb[tid] = __ldg(bB + tid);
    }

    const int tx = tid & 15, ty = tid >> 4;  // ty in [0,32)
    const int r0 = ty * 4, c0 = tx * 8;
    const int NT = (NN + 127) / 128;  // 391 tiles

    for (int tile = blockIdx.x; tile < NT; tile += gridDim.x) {
        int rowBase = tile << 7;
        for (int i = tid; i < 128 * 32; i += 512) {
            int r = i >> 5, q = i & 31;
            int gr = rowBase + r;
            float4 v = make_float4(0.f, 0.f, 0.f, 0.f);
            if (gr < NN) v = __ldg((const float4*)H + (size_t)gr * 32 + q);
            ((float4*)sAT)[i] = v;
        }
        __syncthreads();

        unsigned long long acc[4][4];
        do_gemm(sAT, sW1, r0, c0, acc);
        __syncthreads();  // everyone done reading A before T overwrites it

        // epilogue1: bias + relu -> sAT (as T)
#pragma unroll
        for (int i = 0; i < 4; i++) {
            float2 v0 = unpack2(acc[i][0]);
            float2 v1 = unpack2(acc[i][1]);
            float2 v2 = unpack2(acc[i][2]);
            float2 v3 = unpack2(acc[i][3]);
            v0.x = fmaxf(v0.x + ba[c0 + 0], 0.f); v0.y = fmaxf(v0.y + ba[c0 + 1], 0.f);
            v1.x = fmaxf(v1.x + ba[c0 + 2], 0.f); v1.y = fmaxf(v1.y + ba[c0 + 3], 0.f);
            v2.x = fmaxf(v2.x + ba[c0 + 4], 0.f); v2.y = fmaxf(v2.y + ba[c0 + 5], 0.f);
            v3.x = fmaxf(v3.x + ba[c0 + 6], 0.f); v3.y = fmaxf(v3.y + ba[c0 + 7], 0.f);
            *(float4*)(sAT + (r0 + i) * 128 + c0)     = make_float4(v0.x, v0.y, v1.x, v1.y);
            *(float4*)(sAT + (r0 + i) * 128 + c0 + 4) = make_float4(v2.x, v2.y, v3.x, v3.y);
        }
        __syncthreads();

        do_gemm(sAT, sW2, r0, c0, acc);

        // epilogue2: bias [+relu] -> global
#pragma unroll
        for (int i = 0; i < 4; i++) {
            int gr = rowBase + r0 + i;
            if (gr < NN) {
                float2 v0 = unpack2(acc[i][0]);
                float2 v1 = unpack2(acc[i][1]);
                float2 v2 = unpack2(acc[i][2]);
                float2 v3 = unpack2(acc[i][3]);
                v0.x += bb[c0 + 0]; v0.y += bb[c0 + 1];
                v1.x += bb[c0 + 2]; v1.y += bb[c0 + 3];
                v2.x += bb[c0 + 4]; v2.y += bb[c0 + 5];
                v3.x += bb[c0 + 6]; v3.y += bb[c0 + 7];
                if (RELU_OUT) {
                    v0.x = fmaxf(v0.x, 0.f); v0.y = fmaxf(v0.y, 0.f);
                    v1.x = fmaxf(v1.x, 0.f); v1.y = fmaxf(v1.y, 0.f);
                    v2.x = fmaxf(v2.x, 0.f); v2.y = fmaxf(v2.y, 0.f);
                    v3.x = fmaxf(v3.x, 0.f); v3.y = fmaxf(v3.y, 0.f);
                }
                float* po = out + (size_t)gr * 128 + c0;
                *(float4*)(po)     = make_float4(v0.x, v0.y, v1.x, v1.y);
                *(float4*)(po + 4) = make_float4(v2.x, v2.y, v3.x, v3.y);
            }
        }
        __syncthreads();
    }
}

extern "C" void kernel_launch(void* const* d_in, const int* in_sizes, int n_in,
                              void* d_out, int out_size) {
    const float* features = (const float*)d_in[0];
    const void*  ei       = d_in[1];
    const float* w1a      = (const float*)d_in[2];
    const float* b1a      = (const float*)d_in[3];
    const float* w1b      = (const float*)d_in[4];
    const float* b1b      = (const float*)d_in[5];
    const float* eps1     = (const float*)d_in[6];
    const float* w2a      = (const float*)d_in[7];
    const float* b2a      = (const float*)d_in[8];
    const float* w2b      = (const float*)d_in[9];
    const float* b2b      = (const float*)d_in[10];
    const float* eps2     = (const float*)d_in[11];
    float* out = (float*)d_out;

    float *agg1, *x1, *agg2;
    cudaGetSymbolAddress((void**)&agg1, g_agg1);
    cudaGetSymbolAddress((void**)&x1, g_x1);
    cudaGetSymbolAddress((void**)&agg2, g_agg2);

    cudaFuncSetAttribute(mlp_kernel<true>,
                         cudaFuncAttributeMaxDynamicSharedMemorySize, SMEM_BYTES);
    cudaFuncSetAttribute(mlp_kernel<false>,
                         cudaFuncAttributeMaxDynamicSharedMemorySize, SMEM_BYTES);

    // CSR build (once per call, reused by both layers)
    detect_and_zero_kernel<<<64, 256>>>((const int*)ei);
    hist_kernel<<<(NE + 255) / 256, 256>>>(ei);
    scan_kernel<<<1, 1024>>>();
    fill_kernel<<<(NE + 255) / 256, 256>>>(ei);

    // Layer 1
    agg_kernel<<<(NN * 32 + 255) / 256, 256>>>(features, eps1, agg1);
    mlp_kernel<true><<<148, 512, SMEM_BYTES>>>(agg1, w1a, b1a, w1b, b1b, x1);

    // Layer 2
    agg_kernel<<<(NN * 32 + 255) / 256, 256>>>(x1, eps2, agg2);
    mlp_kernel<false><<<148, 512, SMEM_BYTES>>>(agg2, w2a, b2a, w2b, b2b, out);
}

// round 7
// speedup vs baseline: 1.2410x; 1.2410x over previous
#include <cuda_runtime.h>
#include <cstdint>

#define NN 50000
#define NE 800000

// Scratch (allocation-free rule: __device__ globals)
__device__ float g_agg1[NN * 128];
__device__ float g_x1[NN * 128];
__device__ float g_agg2[NN * 128];
__device__ int g_is64;
__device__ int g_deg[NN];
__device__ int g_rowptr[NN + 1];
__device__ int g_cur[NN];
__device__ int g_esrc[NE];

__device__ __forceinline__ unsigned long long pack2(float x) {
    unsigned long long r;
    asm("mov.b64 %0, {%1, %1};" : "=l"(r) : "f"(x));
    return r;
}
__device__ __forceinline__ float2 unpack2(unsigned long long v) {
    float2 r;
    asm("mov.b64 {%0, %1}, %2;" : "=f"(r.x), "=f"(r.y) : "l"(v));
    return r;
}
__device__ __forceinline__ void fma2(unsigned long long& acc, unsigned long long a, unsigned long long b) {
    asm("fma.rn.f32x2 %0, %1, %2, %0;" : "+l"(acc) : "l"(a), "l"(b));
}

// ======================= CSR build =======================
// Pass 0: detect dtype (block 0) + zero degree array. Must run before hist.
__global__ void detect_and_zero_kernel(const int* __restrict__ w) {
    int i = blockIdx.x * blockDim.x + threadIdx.x;
    for (int k = i; k < NN; k += gridDim.x * blockDim.x) g_deg[k] = 0;
    if (blockIdx.x == 0) {
        __shared__ int any;
        if (threadIdx.x == 0) any = 0;
        __syncthreads();
        int nz = 0;
        for (int k = threadIdx.x; k < 1024; k += blockDim.x) nz |= __ldg(w + 2 * k + 1);
        if (nz) any = 1;
        __syncthreads();
        if (threadIdx.x == 0) g_is64 = any ? 0 : 1;
    }
}

__device__ __forceinline__ int load_dst(const void* ei_raw, int e) {
    if (g_is64) return (int)__ldg((const long long*)ei_raw + NE + e);
    return __ldg((const int*)ei_raw + NE + e);
}
__device__ __forceinline__ void load_edge(const void* ei_raw, int e, int& src, int& dst) {
    if (g_is64) {
        const long long* ei = (const long long*)ei_raw;
        src = (int)__ldg(ei + e);
        dst = (int)__ldg(ei + NE + e);
    } else {
        const int* ei = (const int*)ei_raw;
        src = __ldg(ei + e);
        dst = __ldg(ei + NE + e);
    }
}

__global__ void hist_kernel(const void* __restrict__ ei_raw) {
    int e = blockIdx.x * blockDim.x + threadIdx.x;
    if (e < NE) atomicAdd(&g_deg[load_dst(ei_raw, e)], 1);
}

// single-block exclusive scan: rowptr/cur from deg
__global__ void scan_kernel() {
    __shared__ int part[1024];
    const int tid = threadIdx.x;
    const int CH = (NN + 1023) / 1024;  // 49
    int base = tid * CH;
    int s = 0;
#pragma unroll 4
    for (int i = 0; i < CH; i++) {
        int idx = base + i;
        if (idx < NN) s += g_deg[idx];
    }
    part[tid] = s;
    __syncthreads();
    for (int off = 1; off < 1024; off <<= 1) {
        int t = (tid >= off) ? part[tid - off] : 0;
        __syncthreads();
        part[tid] += t;
        __syncthreads();
    }
    int run = part[tid] - s;  // exclusive prefix
    for (int i = 0; i < CH; i++) {
        int idx = base + i;
        if (idx < NN) {
            g_rowptr[idx] = run;
            g_cur[idx] = run;
            run += g_deg[idx];
        }
    }
    if (tid == 0) g_rowptr[NN] = NE;
}

__global__ void fill_kernel(const void* __restrict__ ei_raw) {
    int e = blockIdx.x * blockDim.x + threadIdx.x;
    if (e < NE) {
        int src, dst;
        load_edge(ei_raw, e, src, dst);
        int p = atomicAdd(&g_cur[dst], 1);
        g_esrc[p] = src;
    }
}

// ======================= CSR aggregation =======================
// One warp per node: agg[i] = (1+eps)*x[i] + sum_{j in N(i)} x[j]
__global__ void agg_kernel(const float* __restrict__ x,
                           const float* __restrict__ eps,
                           float* __restrict__ agg) {
    int node = blockIdx.x * (blockDim.x >> 5) + (threadIdx.x >> 5);
    if (node >= NN) return;
    int lane = threadIdx.x & 31;
    float s = 1.0f + __ldg(eps);
    int beg = __ldg(g_rowptr + node), end = __ldg(g_rowptr + node + 1);

    float4 a = __ldg((const float4*)(x + (size_t)node * 128) + lane);
    float4 acc = make_float4(s * a.x, s * a.y, s * a.z, s * a.w);

    int j = beg;
    for (; j + 4 <= end; j += 4) {
        int s0 = __ldg(g_esrc + j), s1 = __ldg(g_esrc + j + 1);
        int s2 = __ldg(g_esrc + j + 2), s3 = __ldg(g_esrc + j + 3);
        float4 v0 = __ldg((const float4*)(x + (size_t)s0 * 128) + lane);
        float4 v1 = __ldg((const float4*)(x + (size_t)s1 * 128) + lane);
        float4 v2 = __ldg((const float4*)(x + (size_t)s2 * 128) + lane);
        float4 v3 = __ldg((const float4*)(x + (size_t)s3 * 128) + lane);
        acc.x += v0.x + v1.x; acc.y += v0.y + v1.y;
        acc.z += v0.z + v1.z; acc.w += v0.w + v1.w;
        acc.x += v2.x + v3.x; acc.y += v2.y + v3.y;
        acc.z += v2.z + v3.z; acc.w += v2.w + v3.w;
    }
    for (; j < end; j++) {
        int s0 = __ldg(g_esrc + j);
        float4 v = __ldg((const float4*)(x + (size_t)s0 * 128) + lane);
        acc.x += v.x; acc.y += v.y; acc.z += v.z; acc.w += v.w;
    }
    ((float4*)(agg + (size_t)node * 128))[lane] = acc;
}

// ===================== fused MLP: 128x128 tile, 256 thr, 8x8/thread, FFMA2 =====================
#define F_W1  0                       // [128][132] transposed: sW[k*132+c] = w[c*128+k]
#define F_W2  (128 * 132)
#define F_AT  (2 * 128 * 132)         // [128][128] A tile, reused as T tile
#define F_BA  (F_AT + 128 * 128)
#define F_BB  (F_BA + 128)
#define SMEM_FLOATS (F_BB + 128)
#define SMEM_BYTES (SMEM_FLOATS * 4)  // 201728 B

// acc[i][j] covers rows r0+i (i<8), col pair c0+2j (j<4 -> 8 cols)
__device__ __forceinline__ void do_gemm(const float* __restrict__ sA,
                                        const float* __restrict__ sW,
                                        int r0, int c0,
                                        unsigned long long acc[8][4]) {
#pragma unroll
    for (int i = 0; i < 8; i++)
#pragma unroll
        for (int j = 0; j < 4; j++) acc[i][j] = 0ull;

#pragma unroll 4
    for (int k4 = 0; k4 < 128; k4 += 4) {
        float4 a[8];
#pragma unroll
        for (int i = 0; i < 8; i++)
            a[i] = *(const float4*)(sA + (r0 + i) * 128 + k4);
        // hoist W rows for this 4-k chunk
        ulonglong2 w0[4], w1[4];
#pragma unroll
        for (int kk = 0; kk < 4; kk++) {
            w0[kk] = *(const ulonglong2*)(sW + (k4 + kk) * 132 + c0);
            w1[kk] = *(const ulonglong2*)(sW + (k4 + kk) * 132 + c0 + 4);
        }
        const float* af = (const float*)a;
#pragma unroll
        for (int kk = 0; kk < 4; kk++) {
#pragma unroll
            for (int i = 0; i < 8; i++) {
                unsigned long long av = pack2(af[i * 4 + kk]);
                fma2(acc[i][0], av, w0[kk].x);
                fma2(acc[i][1], av, w0[kk].y);
                fma2(acc[i][2], av, w1[kk].x);
                fma2(acc[i][3], av, w1[kk].y);
            }
        }
    }
}

template <bool RELU_OUT>
__global__ void __launch_bounds__(256, 1)
mlp_kernel(const float* __restrict__ H,
           const float* __restrict__ wA, const float* __restrict__ bA,
           const float* __restrict__ wB, const float* __restrict__ bB,
           float* __restrict__ out) {
    extern __shared__ float sm[];
    float* sW1 = sm + F_W1;
    float* sW2 = sm + F_W2;
    float* sAT = sm + F_AT;
    float* ba  = sm + F_BA;
    float* bb  = sm + F_BB;
    const int tid = threadIdx.x;

    for (int i = tid; i < 128 * 128; i += 256) {
        int c = i >> 7, k = i & 127;
        sW1[k * 132 + c] = __ldg(wA + i);
        sW2[k * 132 + c] = __ldg(wB + i);
    }
    if (tid < 128) {
        ba[tid] = __ldg(bA + tid);
        bb[tid] = __ldg(bB + tid);
    }

    const int tx = tid & 15, ty = tid >> 4;
    const int r0 = ty * 8, c0 = tx * 8;
    const int NT = (NN + 127) / 128;  // 391 tiles

    for (int tile = blockIdx.x; tile < NT; tile += gridDim.x) {
        int rowBase = tile << 7;
        for (int i = tid; i < 128 * 32; i += 256) {
            int r = i >> 5, q = i & 31;
            int gr = rowBase + r;
            float4 v = make_float4(0.f, 0.f, 0.f, 0.f);
            if (gr < NN) v = __ldg((const float4*)H + (size_t)gr * 32 + q);
            ((float4*)sAT)[i] = v;
        }
        __syncthreads();

        unsigned long long acc[8][4];
        do_gemm(sAT, sW1, r0, c0, acc);
        __syncthreads();  // everyone done reading A before T overwrites it

        // epilogue1: bias + relu -> sAT (as T)
#pragma unroll
        for (int i = 0; i < 8; i++) {
            float2 v0 = unpack2(acc[i][0]);
            float2 v1 = unpack2(acc[i][1]);
            float2 v2 = unpack2(acc[i][2]);
            float2 v3 = unpack2(acc[i][3]);
            v0.x = fmaxf(v0.x + ba[c0 + 0], 0.f); v0.y = fmaxf(v0.y + ba[c0 + 1], 0.f);
            v1.x = fmaxf(v1.x + ba[c0 + 2], 0.f); v1.y = fmaxf(v1.y + ba[c0 + 3], 0.f);
            v2.x = fmaxf(v2.x + ba[c0 + 4], 0.f); v2.y = fmaxf(v2.y + ba[c0 + 5], 0.f);
            v3.x = fmaxf(v3.x + ba[c0 + 6], 0.f); v3.y = fmaxf(v3.y + ba[c0 + 7], 0.f);
            *(float4*)(sAT + (r0 + i) * 128 + c0)     = make_float4(v0.x, v0.y, v1.x, v1.y);
            *(float4*)(sAT + (r0 + i) * 128 + c0 + 4) = make_float4(v2.x, v2.y, v3.x, v3.y);
        }
        __syncthreads();

        do_gemm(sAT, sW2, r0, c0, acc);

        // epilogue2: bias [+relu] -> global
#pragma unroll
        for (int i = 0; i < 8; i++) {
            int gr = rowBase + r0 + i;
            if (gr < NN) {
                float2 v0 = unpack2(acc[i][0]);
                float2 v1 = unpack2(acc[i][1]);
                float2 v2 = unpack2(acc[i][2]);
                float2 v3 = unpack2(acc[i][3]);
                v0.x += bb[c0 + 0]; v0.y += bb[c0 + 1];
                v1.x += bb[c0 + 2]; v1.y += bb[c0 + 3];
                v2.x += bb[c0 + 4]; v2.y += bb[c0 + 5];
                v3.x += bb[c0 + 6]; v3.y += bb[c0 + 7];
                if (RELU_OUT) {
                    v0.x = fmaxf(v0.x, 0.f); v0.y = fmaxf(v0.y, 0.f);
                    v1.x = fmaxf(v1.x, 0.f); v1.y = fmaxf(v1.y, 0.f);
                    v2.x = fmaxf(v2.x, 0.f); v2.y = fmaxf(v2.y, 0.f);
                    v3.x = fmaxf(v3.x, 0.f); v3.y = fmaxf(v3.y, 0.f);
                }
                float* po = out + (size_t)gr * 128 + c0;
                *(float4*)(po)     = make_float4(v0.x, v0.y, v1.x, v1.y);
                *(float4*)(po + 4) = make_float4(v2.x, v2.y, v3.x, v3.y);
            }
        }
        __syncthreads();
    }
}

extern "C" void kernel_launch(void* const* d_in, const int* in_sizes, int n_in,
                              void* d_out, int out_size) {
    const float* features = (const float*)d_in[0];
    const void*  ei       = d_in[1];
    const float* w1a      = (const float*)d_in[2];
    const float* b1a      = (const float*)d_in[3];
    const float* w1b      = (const float*)d_in[4];
    const float* b1b      = (const float*)d_in[5];
    const float* eps1     = (const float*)d_in[6];
    const float* w2a      = (const float*)d_in[7];
    const float* b2a      = (const float*)d_in[8];
    const float* w2b      = (const float*)d_in[9];
    const float* b2b      = (const float*)d_in[10];
    const float* eps2     = (const float*)d_in[11];
    float* out = (float*)d_out;

    float *agg1, *x1, *agg2;
    cudaGetSymbolAddress((void**)&agg1, g_agg1);
    cudaGetSymbolAddress((void**)&x1, g_x1);
    cudaGetSymbolAddress((void**)&agg2, g_agg2);

    cudaFuncSetAttribute(mlp_kernel<true>,
                         cudaFuncAttributeMaxDynamicSharedMemorySize, SMEM_BYTES);
    cudaFuncSetAttribute(mlp_kernel<false>,
                         cudaFuncAttributeMaxDynamicSharedMemorySize, SMEM_BYTES);

    // CSR build (once per call, reused by both layers)
    detect_and_zero_kernel<<<64, 256>>>((const int*)ei);
    hist_kernel<<<(NE + 511) / 512, 512>>>(ei);
    scan_kernel<<<1, 1024>>>();
    fill_kernel<<<(NE + 511) / 512, 512>>>(ei);

    // Layer 1
    agg_kernel<<<(NN * 32 + 255) / 256, 256>>>(features, eps1, agg1);
    mlp_kernel<true><<<148, 256, SMEM_BYTES>>>(agg1, w1a, b1a, w1b, b1b, x1);

    // Layer 2
    agg_kernel<<<(NN * 32 + 255) / 256, 256>>>(x1, eps2, agg2);
    mlp_kernel<false><<<148, 256, SMEM_BYTES>>>(agg2, w2a, b2a, w2b, b2b, out);
}

// round 10
// speedup vs baseline: 1.6925x; 1.3638x over previous
#include <cuda_runtime.h>
#include <cstdint>

#define NN 50000
#define NE 800000
#define AST 136  // bf16 elems per SMEM row: 128 data + 8 pad (272B stride, 16B-aligned, conflict-free)

// Scratch (allocation-free rule: __device__ globals)
__device__ float g_agg1[NN * 128];
__device__ float g_x1[NN * 128];
__device__ float g_agg2[NN * 128];
__device__ int g_is64;
__device__ int g_deg[NN];
__device__ int g_rowptr[NN + 1];
__device__ int g_cur[NN];
__device__ int g_esrc[NE];

// ======================= CSR build =======================
__global__ void detect_and_zero_kernel(const int* __restrict__ w) {
    int i = blockIdx.x * blockDim.x + threadIdx.x;
    for (int k = i; k < NN; k += gridDim.x * blockDim.x) g_deg[k] = 0;
    if (blockIdx.x == 0) {
        __shared__ int any;
        if (threadIdx.x == 0) any = 0;
        __syncthreads();
        int nz = 0;
        for (int k = threadIdx.x; k < 1024; k += blockDim.x) nz |= __ldg(w + 2 * k + 1);
        if (nz) any = 1;
        __syncthreads();
        if (threadIdx.x == 0) g_is64 = any ? 0 : 1;
    }
}

__device__ __forceinline__ int load_dst(const void* ei_raw, int e) {
    if (g_is64) return (int)__ldg((const long long*)ei_raw + NE + e);
    return __ldg((const int*)ei_raw + NE + e);
}
__device__ __forceinline__ void load_edge(const void* ei_raw, int e, int& src, int& dst) {
    if (g_is64) {
        const long long* ei = (const long long*)ei_raw;
        src = (int)__ldg(ei + e);
        dst = (int)__ldg(ei + NE + e);
    } else {
        const int* ei = (const int*)ei_raw;
        src = __ldg(ei + e);
        dst = __ldg(ei + NE + e);
    }
}

__global__ void hist_kernel(const void* __restrict__ ei_raw) {
    int e = blockIdx.x * blockDim.x + threadIdx.x;
    if (e < NE) atomicAdd(&g_deg[load_dst(ei_raw, e)], 1);
}

__global__ void scan_kernel() {
    __shared__ int part[1024];
    const int tid = threadIdx.x;
    const int CH = (NN + 1023) / 1024;  // 49
    int base = tid * CH;
    int s = 0;
#pragma unroll 4
    for (int i = 0; i < CH; i++) {
        int idx = base + i;
        if (idx < NN) s += g_deg[idx];
    }
    part[tid] = s;
    __syncthreads();
    for (int off = 1; off < 1024; off <<= 1) {
        int t = (tid >= off) ? part[tid - off] : 0;
        __syncthreads();
        part[tid] += t;
        __syncthreads();
    }
    int run = part[tid] - s;
    for (int i = 0; i < CH; i++) {
        int idx = base + i;
        if (idx < NN) {
            g_rowptr[idx] = run;
            g_cur[idx] = run;
            run += g_deg[idx];
        }
    }
    if (tid == 0) g_rowptr[NN] = NE;
}

__global__ void fill_kernel(const void* __restrict__ ei_raw) {
    int e = blockIdx.x * blockDim.x + threadIdx.x;
    if (e < NE) {
        int src, dst;
        load_edge(ei_raw, e, src, dst);
        int p = atomicAdd(&g_cur[dst], 1);
        g_esrc[p] = src;
    }
}

// ======================= CSR aggregation =======================
__global__ void agg_kernel(const float* __restrict__ x,
                           const float* __restrict__ eps,
                           float* __restrict__ agg) {
    int node = blockIdx.x * (blockDim.x >> 5) + (threadIdx.x >> 5);
    if (node >= NN) return;
    int lane = threadIdx.x & 31;
    float s = 1.0f + __ldg(eps);
    int beg = __ldg(g_rowptr + node), end = __ldg(g_rowptr + node + 1);

    float4 a = __ldg((const float4*)(x + (size_t)node * 128) + lane);
    float4 acc = make_float4(s * a.x, s * a.y, s * a.z, s * a.w);

    int j = beg;
    for (; j + 4 <= end; j += 4) {
        int s0 = __ldg(g_esrc + j), s1 = __ldg(g_esrc + j + 1);
        int s2 = __ldg(g_esrc + j + 2), s3 = __ldg(g_esrc + j + 3);
        float4 v0 = __ldg((const float4*)(x + (size_t)s0 * 128) + lane);
        float4 v1 = __ldg((const float4*)(x + (size_t)s1 * 128) + lane);
        float4 v2 = __ldg((const float4*)(x + (size_t)s2 * 128) + lane);
        float4 v3 = __ldg((const float4*)(x + (size_t)s3 * 128) + lane);
        acc.x += v0.x + v1.x; acc.y += v0.y + v1.y;
        acc.z += v0.z + v1.z; acc.w += v0.w + v1.w;
        acc.x += v2.x + v3.x; acc.y += v2.y + v3.y;
        acc.z += v2.z + v3.z; acc.w += v2.w + v3.w;
    }
    for (; j < end; j++) {
        int s0 = __ldg(g_esrc + j);
        float4 v = __ldg((const float4*)(x + (size_t)s0 * 128) + lane);
        acc.x += v.x; acc.y += v.y; acc.z += v.z; acc.w += v.w;
    }
    ((float4*)(agg + (size_t)node * 128))[lane] = acc;
}

// ===================== tensor-core MLP (mma.sync bf16 hi/lo split) =====================
#define TBUF (128 * AST * 2)   // 34816 B per 128x128 bf16 buffer
#define OB_W1H 0
#define OB_W1L (OB_W1H + TBUF)
#define OB_W2H (OB_W1L + TBUF)
#define OB_W2L (OB_W2H + TBUF)
#define OB_ATH (OB_W2L + TBUF)
#define OB_ATL (OB_ATH + TBUF)
#define OB_BA  (OB_ATL + TBUF)
#define OB_BB  (OB_BA + 512)
#define MLP_SMEM (OB_BB + 512)   // 209920 B

__device__ __forceinline__ uint32_t cvta_s(const void* p) {
    uint32_t r;
    asm("{ .reg .u64 t; cvta.to.shared.u64 t, %1; cvt.u32.u64 %0, t; }" : "=r"(r) : "l"(p));
    return r;
}
// pack (a -> low half, b -> high half) as bf16x2
__device__ __forceinline__ uint32_t bfpack(float a, float b) {
    uint32_t r;
    asm("cvt.rn.bf16x2.f32 %0, %1, %2;" : "=r"(r) : "f"(b), "f"(a));
    return r;
}
__device__ __forceinline__ void split2(float a, float b, uint32_t& hi, uint32_t& lo) {
    hi = bfpack(a, b);
    float ah = __uint_as_float(hi << 16);
    float bh = __uint_as_float(hi & 0xFFFF0000u);
    lo = bfpack(a - ah, b - bh);
}
__device__ __forceinline__ void split4(float4 v, uint2& hi, uint2& lo) {
    split2(v.x, v.y, hi.x, lo.x);
    split2(v.z, v.w, hi.y, lo.y);
}

__device__ __forceinline__ void ldsm_x4(uint32_t r[4], uint32_t a) {
    asm volatile("ldmatrix.sync.aligned.m8n8.x4.shared.b16 {%0,%1,%2,%3}, [%4];"
                 : "=r"(r[0]), "=r"(r[1]), "=r"(r[2]), "=r"(r[3]) : "r"(a));
}
// NON-trans: W stored [n][k] row-major == B col-major fragment for row.col mma
__device__ __forceinline__ void ldsm_x2(uint32_t r[2], uint32_t a) {
    asm volatile("ldmatrix.sync.aligned.m8n8.x2.shared.b16 {%0,%1}, [%2];"
                 : "=r"(r[0]), "=r"(r[1]) : "r"(a));
}
__device__ __forceinline__ void mma16816(float c[4], const uint32_t a[4], const uint32_t b[2]) {
    asm volatile("mma.sync.aligned.m16n8k16.row.col.f32.bf16.bf16.f32 "
                 "{%0,%1,%2,%3},{%4,%5,%6,%7},{%8,%9},{%0,%1,%2,%3};"
                 : "+f"(c[0]), "+f"(c[1]), "+f"(c[2]), "+f"(c[3])
                 : "r"(a[0]), "r"(a[1]), "r"(a[2]), "r"(a[3]), "r"(b[0]), "r"(b[1]));
}

// out(warp slice) = A(hi+lo) @ W(hi+lo)^T, dropping lo*lo. A rows r_base..+31, W cols c_base..+63.
__device__ __forceinline__ void mma_gemm(uint32_t sb, int offAH, int offAL, int offWH, int offWL,
                                         int lane, int r_base, int c_base, float c[2][8][4]) {
#pragma unroll
    for (int t = 0; t < 2; t++)
#pragma unroll
        for (int n = 0; n < 8; n++)
#pragma unroll
            for (int q = 0; q < 4; q++) c[t][n][q] = 0.f;

    const int arow = lane & 15, acol = (lane >> 4) << 3;
    const int bwrow = lane & 7, bcol = ((lane >> 3) & 1) << 3;
#pragma unroll
    for (int kt = 0; kt < 128; kt += 16) {
        uint32_t a[2][2][4];
#pragma unroll
        for (int t = 0; t < 2; t++) {
            uint32_t bo = (uint32_t)(((r_base + t * 16 + arow) * AST + kt + acol) * 2);
            ldsm_x4(a[t][0], sb + offAH + bo);
            ldsm_x4(a[t][1], sb + offAL + bo);
        }
#pragma unroll
        for (int n = 0; n < 8; n++) {
            uint32_t bo = (uint32_t)(((c_base + n * 8 + bwrow) * AST + kt + bcol) * 2);
            uint32_t bh[2], bl[2];
            ldsm_x2(bh, sb + offWH + bo);
            ldsm_x2(bl, sb + offWL + bo);
#pragma unroll
            for (int t = 0; t < 2; t++) {
                mma16816(c[t][n], a[t][0], bh);  // hi*hi
                mma16816(c[t][n], a[t][0], bl);  // hi*lo
                mma16816(c[t][n], a[t][1], bh);  // lo*hi
            }
        }
    }
}

template <bool RELU_OUT>
__global__ void __launch_bounds__(256, 1)
mlp_kernel(const float* __restrict__ H,
           const float* __restrict__ wA, const float* __restrict__ bA,
           const float* __restrict__ wB, const float* __restrict__ bB,
           float* __restrict__ out) {
    extern __shared__ char smem[];
    const uint32_t sb = cvta_s(smem);
    const int tid = threadIdx.x, lane = tid & 31, wid = tid >> 5;
    const int r_base = (wid & 3) * 32, c_base = (wid >> 2) * 64;
    float* ba = (float*)(smem + OB_BA);
    float* bb = (float*)(smem + OB_BB);

    // Weights -> bf16 hi/lo in SMEM (row-major [c][k], stride AST)
    for (int i = tid; i < 4096; i += 256) {
        int row = i >> 5, col = (i & 31) << 2;
        uint2 hi, lo;
        float4 v = __ldg((const float4*)wA + i);
        split4(v, hi, lo);
        *(uint2*)(smem + OB_W1H + (row * AST + col) * 2) = hi;
        *(uint2*)(smem + OB_W1L + (row * AST + col) * 2) = lo;
        v = __ldg((const float4*)wB + i);
        split4(v, hi, lo);
        *(uint2*)(smem + OB_W2H + (row * AST + col) * 2) = hi;
        *(uint2*)(smem + OB_W2L + (row * AST + col) * 2) = lo;
    }
    if (tid < 128) {
        ba[tid] = __ldg(bA + tid);
        bb[tid] = __ldg(bB + tid);
    }

    const int NT = (NN + 127) / 128;  // 391 tiles
    for (int tile = blockIdx.x; tile < NT; tile += gridDim.x) {
        int rowBase = tile << 7;
        // fill A tile (bf16 hi/lo)
        for (int i = tid; i < 4096; i += 256) {
            int r = i >> 5, col = (i & 31) << 2;
            int gr = rowBase + r;
            float4 v = make_float4(0.f, 0.f, 0.f, 0.f);
            if (gr < NN) v = __ldg((const float4*)H + (size_t)gr * 32 + (i & 31));
            uint2 hi, lo;
            split4(v, hi, lo);
            *(uint2*)(smem + OB_ATH + (r * AST + col) * 2) = hi;
            *(uint2*)(smem + OB_ATL + (r * AST + col) * 2) = lo;
        }
        __syncthreads();

        float c[2][8][4];
        mma_gemm(sb, OB_ATH, OB_ATL, OB_W1H, OB_W1L, lane, r_base, c_base, c);
        __syncthreads();  // all warps done reading A before T overwrites it

        // epilogue1: bias + relu -> T (bf16 hi/lo, same buffers)
#pragma unroll
        for (int t = 0; t < 2; t++)
#pragma unroll
            for (int n = 0; n < 8; n++) {
                int r0 = r_base + t * 16 + (lane >> 2);
                int col = c_base + n * 8 + ((lane & 3) << 1);
                float b0 = ba[col], b1 = ba[col + 1];
                float v0 = fmaxf(c[t][n][0] + b0, 0.f);
                float v1 = fmaxf(c[t][n][1] + b1, 0.f);
                uint32_t h, l;
                split2(v0, v1, h, l);
                *(uint32_t*)(smem + OB_ATH + (r0 * AST + col) * 2) = h;
                *(uint32_t*)(smem + OB_ATL + (r0 * AST + col) * 2) = l;
                float v2 = fmaxf(c[t][n][2] + b0, 0.f);
                float v3 = fmaxf(c[t][n][3] + b1, 0.f);
                split2(v2, v3, h, l);
                *(uint32_t*)(smem + OB_ATH + ((r0 + 8) * AST + col) * 2) = h;
                *(uint32_t*)(smem + OB_ATL + ((r0 + 8) * AST + col) * 2) = l;
            }
        __syncthreads();

        mma_gemm(sb, OB_ATH, OB_ATL, OB_W2H, OB_W2L, lane, r_base, c_base, c);

        // epilogue2: bias [+relu] -> global
#pragma unroll
        for (int t = 0; t < 2; t++)
#pragma unroll
            for (int n = 0; n < 8; n++) {
                int r0 = r_base + t * 16 + (lane >> 2);
                int col = c_base + n * 8 + ((lane & 3) << 1);
                float b0 = bb[col], b1 = bb[col + 1];
                int gr = rowBase + r0;
                if (gr < NN) {
                    float v0 = c[t][n][0] + b0, v1 = c[t][n][1] + b1;
                    if (RELU_OUT) { v0 = fmaxf(v0, 0.f); v1 = fmaxf(v1, 0.f); }
                    *(float2*)(out + (size_t)gr * 128 + col) = make_float2(v0, v1);
                }
                if (gr + 8 < NN) {
                    float v2 = c[t][n][2] + b0, v3 = c[t][n][3] + b1;
                    if (RELU_OUT) { v2 = fmaxf(v2, 0.f); v3 = fmaxf(v3, 0.f); }
                    *(float2*)(out + (size_t)(gr + 8) * 128 + col) = make_float2(v2, v3);
                }
            }
        __syncthreads();  // before next tile's A fill
    }
}

extern "C" void kernel_launch(void* const* d_in, const int* in_sizes, int n_in,
                              void* d_out, int out_size) {
    const float* features = (const float*)d_in[0];
    const void*  ei       = d_in[1];
    const float* w1a      = (const float*)d_in[2];
    const float* b1a      = (const float*)d_in[3];
    const float* w1b      = (const float*)d_in[4];
    const float* b1b      = (const float*)d_in[5];
    const float* eps1     = (const float*)d_in[6];
    const float* w2a      = (const float*)d_in[7];
    const float* b2a      = (const float*)d_in[8];
    const float* w2b      = (const float*)d_in[9];
    const float* b2b      = (const float*)d_in[10];
    const float* eps2     = (const float*)d_in[11];
    float* out = (float*)d_out;

    float *agg1, *x1, *agg2;
    cudaGetSymbolAddress((void**)&agg1, g_agg1);
    cudaGetSymbolAddress((void**)&x1, g_x1);
    cudaGetSymbolAddress((void**)&agg2, g_agg2);

    cudaFuncSetAttribute(mlp_kernel<true>,
                         cudaFuncAttributeMaxDynamicSharedMemorySize, MLP_SMEM);
    cudaFuncSetAttribute(mlp_kernel<false>,
                         cudaFuncAttributeMaxDynamicSharedMemorySize, MLP_SMEM);

    // CSR build (once per call, reused by both layers)
    detect_and_zero_kernel<<<64, 256>>>((const int*)ei);
    hist_kernel<<<(NE + 511) / 512, 512>>>(ei);
    scan_kernel<<<1, 1024>>>();
    fill_kernel<<<(NE + 511) / 512, 512>>>(ei);

    // Layer 1
    agg_kernel<<<(NN * 32 + 255) / 256, 256>>>(features, eps1, agg1);
    mlp_kernel<true><<<148, 256, MLP_SMEM>>>(agg1, w1a, b1a, w1b, b1b, x1);

    // Layer 2
    agg_kernel<<<(NN * 32 + 255) / 256, 256>>>(x1, eps2, agg2);
    mlp_kernel<false><<<148, 256, MLP_SMEM>>>(agg2, w2a, b2a, w2b, b2b, out);
}